// round 1
// baseline (speedup 1.0000x reference)
#include <cuda_runtime.h>
#include <math.h>

// Problem constants (from metadata: spikes (B,1024) f32, weights (1024,256) f32)
#define NPRE   1024
#define NPOST  256
#define MAXB   128
#define KCH    32          // k-chunk staged through shared memory
#define NSPLIT 2           // blocks per batch (each handles NPOST/NSPLIT neurons)
#define NT     (NPOST / NSPLIT)   // 128 threads per scan block

#define INV_E_F  0.36787944117144233f
#define E_F      2.718281828459045f

// Scratch (no allocations allowed): sorted spike data per batch row.
__device__ float g_sorted[MAXB * NPRE];
__device__ float g_exp[MAXB * NPRE];   // exp(s)
__device__ float g_se[MAXB * NPRE];    // s * exp(s)
__device__ int   g_idx[MAXB * NPRE];   // argsort indices

// ---------------------------------------------------------------------------
// Kernel 1: stable ascending sort of each batch row of spikes.
// Key = (order-preserving float bits << 32) | index  -> stable, matches
// jnp.argsort. 1024 elements, bitonic in shared memory, 512 threads.
// ---------------------------------------------------------------------------
__global__ void __launch_bounds__(512) sort_kernel(const float* __restrict__ spikes)
{
    __shared__ unsigned long long keys[NPRE];
    const int b   = blockIdx.x;
    const int tid = threadIdx.x;

    for (int i = tid; i < NPRE; i += 512) {
        float v = spikes[b * NPRE + i];
        unsigned int bits = __float_as_uint(v);
        bits = (bits & 0x80000000u) ? ~bits : (bits | 0x80000000u);
        keys[i] = ((unsigned long long)bits << 32) | (unsigned int)i;
    }
    __syncthreads();

    for (int k = 2; k <= NPRE; k <<= 1) {
        for (int j = k >> 1; j > 0; j >>= 1) {
            #pragma unroll
            for (int rep = 0; rep < NPRE / 512; ++rep) {
                int i = tid + rep * 512;
                int ixj = i ^ j;
                if (ixj > i) {
                    unsigned long long A = keys[i];
                    unsigned long long C = keys[ixj];
                    bool up = ((i & k) == 0);
                    if ((A > C) == up) { keys[i] = C; keys[ixj] = A; }
                }
            }
            __syncthreads();
        }
    }

    for (int i = tid; i < NPRE; i += 512) {
        unsigned long long kk = keys[i];
        unsigned int hi = (unsigned int)(kk >> 32);
        unsigned int bits = (hi & 0x80000000u) ? (hi ^ 0x80000000u) : ~hi;
        float s = __uint_as_float(bits);
        float e = expf(s);
        g_sorted[b * NPRE + i] = s;
        g_exp[b * NPRE + i]    = e;
        g_se[b * NPRE + i]     = s * e;
        g_idx[b * NPRE + i]    = (int)(kk & 0xFFFFFFFFu);
    }
}

// ---------------------------------------------------------------------------
// Lambert W0 on [-1/e, 0): identical clip + init + Halley form as reference,
// 6 iterations (reference's 12 are converged by ~3-4; fp32, tol 1e-3).
// ---------------------------------------------------------------------------
__device__ __forceinline__ float lambertw0_dev(float z)
{
    float zc = fminf(fmaxf(z, -INV_E_F + 1e-8f), -1e-30f);
    float w;
    if (zc < -0.2f)
        w = -1.0f + sqrtf(2.0f * fmaf(E_F, zc, 1.0f));
    else
        w = zc * (1.0f - zc);
    #pragma unroll
    for (int it = 0; it < 6; ++it) {
        float ew  = __expf(w);
        float f   = fmaf(w, ew, -zc);
        float wp1 = w + 1.0f;
        // step = f / (ew*wp1 - (w+2)*f/(2*wp1)), rearranged to one divide
        float denom = fmaf(2.0f * ew * wp1, wp1, -(w + 2.0f) * f);
        w = w - __fdividef(f * 2.0f * wp1, denom);
    }
    return w;
}

// ---------------------------------------------------------------------------
// Kernel 2: per (batch, neuron) sequential causal scan with:
//   * O(1) firing gate:  a*s_next - b >= exp(s_next)
//     (exactly equivalent to  z >= -1/e  AND  t <= s_next  for s_next < 1+r;
//      s_next = +inf on the last k makes the gate pass and defers to the
//      exact check, reproducing the reference's last-row exemption)
//   * full Lambert W evaluated only on gate pass (~once per neuron)
//   * first valid candidate == min over k  (positive weights => a monotone)
//   * block-wide early exit
// 2 blocks per batch, 128 threads each (one per output neuron).
// ---------------------------------------------------------------------------
__global__ void __launch_bounds__(NT) scan_kernel(const float* __restrict__ Wmat,
                                                  float* __restrict__ out)
{
    __shared__ float sh_w[KCH][NT];
    __shared__ float sh_s[KCH + 1];
    __shared__ float sh_e[KCH + 1];
    __shared__ float sh_se[KCH];

    const int b    = blockIdx.x / NSPLIT;
    const int half = blockIdx.x % NSPLIT;
    const int tid  = threadIdx.x;
    const int n    = half * NT + tid;
    const int base = b * NPRE;

    float acc_a = 0.0f, acc_b = 0.0f;
    float res = INFINITY;
    bool done = false;

    for (int k0 = 0; k0 < NPRE; k0 += KCH) {
        // stage metadata for this chunk (+1 lookahead for s_next / e_next)
        if (tid <= KCH) {
            int k = k0 + tid;
            if (k < NPRE) { sh_s[tid] = g_sorted[base + k]; sh_e[tid] = g_exp[base + k]; }
            else          { sh_s[tid] = INFINITY;           sh_e[tid] = INFINITY; }
            if (tid < KCH) sh_se[tid] = g_se[base + k];
        }
        // stage gathered weight rows (coalesced, high MLP)
        #pragma unroll 8
        for (int kk = 0; kk < KCH; ++kk) {
            int row = g_idx[base + k0 + kk];          // uniform across threads
            sh_w[kk][tid] = Wmat[row * NPOST + n];    // 512B coalesced per row
        }
        __syncthreads();

        if (!done) {
            for (int kk = 0; kk < KCH; ++kk) {
                float w = sh_w[kk][tid];
                acc_a = fmaf(w, sh_e[kk],  acc_a);
                acc_b = fmaf(w, sh_se[kk], acc_b);
                float snext = sh_s[kk + 1];
                // cheap exact gate: fires iff z >= -1/e AND t <= s_next
                if (fmaf(acc_a, snext, -acc_b) >= sh_e[kk + 1]) {
                    float r = __fdividef(acc_b, acc_a);           // r in [0,1)
                    float z = -__fdividef(__expf(r), acc_a);
                    bool valid = (acc_a > 0.0f) && (z >= -INV_E_F);
                    float t = r - lambertw0_dev(z);
                    if (valid && t >= sh_s[kk]) {                 // causal lower bound
                        res = t;
                        done = true;
                        break;                                    // first valid == min
                    }
                }
            }
        }
        if (__syncthreads_and((int)done)) break;   // also guards shared reuse
    }

    out[b * NPOST + n] = res;
}

// ---------------------------------------------------------------------------
extern "C" void kernel_launch(void* const* d_in, const int* in_sizes, int n_in,
                              void* d_out, int out_size)
{
    const float* spikes  = (const float*)d_in[0];
    const float* weights = (const float*)d_in[1];
    // robustness: spikes is the smaller tensor (B*1024 vs 1024*256)
    if (n_in >= 2 && in_sizes[0] > in_sizes[1]) {
        const float* t = spikes; spikes = weights; weights = t;
        // (sizes swap implicitly handled below via the smaller one)
        int B0 = in_sizes[1] / NPRE;
        sort_kernel<<<B0, 512>>>(spikes);
        scan_kernel<<<B0 * NSPLIT, NT>>>(weights, (float*)d_out);
        return;
    }
    int B = in_sizes[0] / NPRE;
    sort_kernel<<<B, 512>>>(spikes);
    scan_kernel<<<B * NSPLIT, NT>>>(weights, (float*)d_out);
}

// round 4
// speedup vs baseline: 1.0220x; 1.0220x over previous
#include <cuda_runtime.h>
#include <math.h>

#define NPRE   1024
#define NPOST  256
#define MAXB   128

// scan kernel geometry
#define CH     64                 // k-chunk length
#define NT     64                 // neurons per block
#define NSUB   8                  // k sub-slices per neuron
#define KSUB   (CH / NSUB)        // 8 k per thread per chunk
#define NTHR   (NT * NSUB)        // 512 threads
#define NGRP   (NPOST / NT)       // 4 neuron groups per batch

#define INV_E_F  0.36787944117144233f
#define E_F      2.718281828459045f

// Scratch (no allocations allowed): sorted spike data per batch row.
__device__ float g_sorted[MAXB * NPRE];
__device__ float g_exp[MAXB * NPRE];   // exp(s)
__device__ float g_se[MAXB * NPRE];    // s * exp(s)
__device__ int   g_idx[MAXB * NPRE];   // argsort indices

// ---------------------------------------------------------------------------
// Kernel 1: stable ascending sort of each batch row (matches jnp.argsort).
// Key = (order-preserving float bits << 32) | index. Bitonic: shared-memory
// phases for j>=32, register shfl_xor butterflies for j<=16.
// BUGFIX vs R2/R3: register phase must only run strides j < k (stage k of a
// bitonic network uses j = k/2 .. 1; running j=16..1 at k=2 scrambles).
// ---------------------------------------------------------------------------
__global__ void __launch_bounds__(512) sort_kernel(const float* __restrict__ spikes)
{
    __shared__ unsigned long long keys[NPRE];
    const int b   = blockIdx.x;
    const int tid = threadIdx.x;

    for (int i = tid; i < NPRE; i += 512) {
        float v = spikes[b * NPRE + i];
        unsigned int bits = __float_as_uint(v);
        bits = (bits & 0x80000000u) ? ~bits : (bits | 0x80000000u);
        keys[i] = ((unsigned long long)bits << 32) | (unsigned int)i;
    }
    __syncthreads();

    for (int k = 2; k <= NPRE; k <<= 1) {
        for (int j = k >> 1; j >= 32; j >>= 1) {
            #pragma unroll
            for (int rep = 0; rep < NPRE / 512; ++rep) {
                int i = tid + rep * 512;
                int ixj = i ^ j;
                if (ixj > i) {
                    unsigned long long A = keys[i];
                    unsigned long long C = keys[ixj];
                    bool up = ((i & k) == 0);
                    if ((A > C) == up) { keys[i] = C; keys[ixj] = A; }
                }
            }
            __syncthreads();
        }
        // register phases j = min(k/2,16)..1 via warp shuffles
        unsigned long long v0 = keys[tid];
        unsigned long long v1 = keys[tid + 512];
        const bool up0 = ((tid & k) == 0);
        const bool up1 = (((tid + 512) & k) == 0);
        #pragma unroll
        for (int j = 16; j >= 1; j >>= 1) {
            if (j < k) {                       // <-- the fix
                bool lower = ((tid & j) == 0); // same for tid and tid+512 (j<32)
                unsigned long long p0 = __shfl_xor_sync(0xffffffffu, v0, j);
                unsigned long long p1 = __shfl_xor_sync(0xffffffffu, v1, j);
                bool km0 = (lower == up0);
                bool km1 = (lower == up1);
                unsigned long long mn0 = (v0 < p0) ? v0 : p0;
                unsigned long long mx0 = (v0 < p0) ? p0 : v0;
                unsigned long long mn1 = (v1 < p1) ? v1 : p1;
                unsigned long long mx1 = (v1 < p1) ? p1 : v1;
                v0 = km0 ? mn0 : mx0;
                v1 = km1 ? mn1 : mx1;
            }
        }
        keys[tid]       = v0;
        keys[tid + 512] = v1;
        __syncthreads();
    }

    for (int i = tid; i < NPRE; i += 512) {
        unsigned long long kk = keys[i];
        unsigned int hi = (unsigned int)(kk >> 32);
        unsigned int bits = (hi & 0x80000000u) ? (hi ^ 0x80000000u) : ~hi;
        float s = __uint_as_float(bits);
        float e = expf(s);
        g_sorted[b * NPRE + i] = s;
        g_exp[b * NPRE + i]    = e;
        g_se[b * NPRE + i]     = s * e;
        g_idx[b * NPRE + i]    = (int)(kk & 0xFFFFFFFFu);
    }
}

// ---------------------------------------------------------------------------
// Lambert W0 on [-1/e, 0): same clip/init/Halley form as the reference.
// ---------------------------------------------------------------------------
__device__ __forceinline__ float lambertw0_dev(float z)
{
    float zc = fminf(fmaxf(z, -INV_E_F + 1e-8f), -1e-30f);
    float w;
    if (zc < -0.2f)
        w = -1.0f + sqrtf(2.0f * fmaf(E_F, zc, 1.0f));
    else
        w = zc * (1.0f - zc);
    #pragma unroll
    for (int it = 0; it < 6; ++it) {
        float ew  = __expf(w);
        float f   = fmaf(w, ew, -zc);
        float wp1 = w + 1.0f;
        float denom = fmaf(2.0f * ew * wp1, wp1, -(w + 2.0f) * f);
        w = w - __fdividef(f * 2.0f * wp1, denom);
    }
    return w;
}

// ---------------------------------------------------------------------------
// Kernel 2: chunked causal scan, k-parallel partial sums, sound slice prune.
//   Block = (batch, 64-neuron group), 512 threads = 64 n x 8 k-slices.
//   Per chunk of 64 sorted inputs:
//     A: stage s, e, s*e, idx (+1 lookahead) in shared
//     B: each (n,q) thread gathers its 8 weights (coalesced), accumulates
//        slice partial sums (pa, pb), stages w into shared
//     C: per-neuron leader walks the 8 slices. For slice j, every inner
//        gate a_k*s_{k+1}-b_k >= e^{s_{k+1}} is bounded by the CONCAVE
//        H(s) = a_hi*s - b_lo - e^s  (a_k<=a_hi, b_k>=b_lo, w>=0 & s>=0),
//        maximized at s = clamp(ln a_hi, s_lo, s_hi). max < -1e-2 =>
//        provably no candidate in the slice, jump via exact partial sums.
//        Else: exact 8-element serial rescan (identical per-k gate +
//        Lambert semantics as the verified R1 kernel). First valid
//        candidate == min (weights >= 0 => monotone causal crossing).
//   Block-wide early exit when all 64 neurons are done.
// ---------------------------------------------------------------------------
__global__ void __launch_bounds__(NTHR) scan_kernel(const float* __restrict__ Wmat,
                                                    float* __restrict__ out)
{
    __shared__ float sh_w[CH][NT];          // 16 KB
    __shared__ float sh_s[CH + 1];
    __shared__ float sh_e[CH + 1];
    __shared__ float sh_se[CH];
    __shared__ int   sh_idx[CH];
    __shared__ float sh_pa[NSUB][NT];
    __shared__ float sh_pb[NSUB][NT];

    const int b    = blockIdx.x / NGRP;
    const int grp  = blockIdx.x % NGRP;
    const int tid  = threadIdx.x;
    const int q    = tid >> 6;          // k sub-slice 0..7
    const int n    = tid & 63;          // neuron within group
    const int ng   = grp * NT + n;      // global output neuron
    const int base = b * NPRE;

    bool  done  = false;
    float res   = INFINITY;
    float a_run = 0.0f, b_run = 0.0f;   // leader's exact prefix sums

    for (int k0 = 0; k0 < NPRE; k0 += CH) {
        // ---- phase A: stage chunk metadata ----
        if (tid < CH) {
            int k = base + k0 + tid;
            sh_s[tid]   = g_sorted[k];
            sh_e[tid]   = g_exp[k];
            sh_se[tid]  = g_se[k];
            sh_idx[tid] = g_idx[k];
        } else if (tid == CH) {
            int k = k0 + CH;
            if (k < NPRE) { sh_s[CH] = g_sorted[base + k]; sh_e[CH] = g_exp[base + k]; }
            else          { sh_s[CH] = INFINITY;           sh_e[CH] = INFINITY; }
        }
        __syncthreads();

        // ---- phase B: parallel slice sums + weight staging ----
        float pa = 0.0f, pb = 0.0f;
        #pragma unroll
        for (int kk = 0; kk < KSUB; ++kk) {
            int kc = q * KSUB + kk;
            float w = Wmat[sh_idx[kc] * NPOST + ng];   // 128B coalesced per warp
            sh_w[kc][n] = w;
            pa = fmaf(w, sh_e[kc],  pa);
            pb = fmaf(w, sh_se[kc], pb);
        }
        sh_pa[q][n] = pa;
        sh_pb[q][n] = pb;
        __syncthreads();

        // ---- phase C: leader slice walk with sound concavity prune ----
        if (q == 0 && !done) {
            float aa = a_run, bb = b_run;
            #pragma unroll 1
            for (int j = 0; j < NSUB; ++j) {
                float a_hi = aa + sh_pa[j][n];
                float lo   = sh_s[j * KSUB + 1];
                float hi   = sh_s[j * KSUB + KSUB];
                float la   = __logf(fmaxf(a_hi, 1e-30f));
                float m;
                if (la <= lo)       m = fmaf(a_hi, lo, -bb) - sh_e[j * KSUB + 1];
                else if (la >= hi)  m = fmaf(a_hi, hi, -bb) - sh_e[j * KSUB + KSUB];
                else                m = fmaf(a_hi, la - 1.0f, -bb);   // e^la == a_hi
                if (m >= -1e-2f) {
                    // exact serial rescan of slice j
                    #pragma unroll
                    for (int kk = j * KSUB; kk < j * KSUB + KSUB; ++kk) {
                        float w = sh_w[kk][n];
                        aa = fmaf(w, sh_e[kk],  aa);
                        bb = fmaf(w, sh_se[kk], bb);
                        // exact gate: z >= -1/e AND t <= s_next
                        if (fmaf(aa, sh_s[kk + 1], -bb) >= sh_e[kk + 1]) {
                            float r = __fdividef(bb, aa);
                            float z = -__fdividef(__expf(r), aa);
                            bool valid = (aa > 0.0f) && (z >= -INV_E_F);
                            float t = r - lambertw0_dev(z);
                            if (valid && t >= sh_s[kk]) {   // causal lower bound
                                res  = t;
                                done = true;
                                break;                      // first valid == min
                            }
                        }
                    }
                    if (done) break;
                } else {
                    aa += sh_pa[j][n];
                    bb += sh_pb[j][n];
                }
            }
            a_run = aa;
            b_run = bb;
        }

        int vote = (q != 0) || done;
        if (__syncthreads_and(vote)) break;   // barrier also guards shared reuse
    }

    if (q == 0) out[b * NPOST + ng] = res;
}

// ---------------------------------------------------------------------------
extern "C" void kernel_launch(void* const* d_in, const int* in_sizes, int n_in,
                              void* d_out, int out_size)
{
    const float* spikes  = (const float*)d_in[0];
    const float* weights = (const float*)d_in[1];
    int sz = in_sizes[0];
    if (n_in >= 2 && in_sizes[0] > in_sizes[1]) {   // robustness to input order
        const float* t = spikes; spikes = weights; weights = t;
        sz = in_sizes[1];
    }
    int B = sz / NPRE;
    sort_kernel<<<B, 512>>>(spikes);
    scan_kernel<<<B * NGRP, NTHR>>>(weights, (float*)d_out);
}

// round 5
// speedup vs baseline: 1.1976x; 1.1718x over previous
#include <cuda_runtime.h>
#include <math.h>

#define NPRE   1024
#define NPOST  256
#define MAXB   128

// scan kernel geometry
#define CH     64                 // k-chunk length
#define NT     64                 // neurons per block
#define NSUB   8                  // k sub-slices per chunk
#define KSUB   (CH / NSUB)        // 8 k per thread per chunk
#define NTHR   (NT * NSUB)        // 512 threads
#define NGRP   (NPOST / NT)       // 4 neuron groups per batch
#define NCHUNK (NPRE / CH)        // 16 chunks

#define INV_E_F  0.36787944117144233f
#define E_F      2.718281828459045f

// Scratch (no allocations allowed): sorted spike data per batch row.
__device__ float g_sorted[MAXB * NPRE];
__device__ float g_exp[MAXB * NPRE];   // exp(s)
__device__ float g_se[MAXB * NPRE];    // s * exp(s)
__device__ int   g_idx[MAXB * NPRE];   // argsort indices

// ---------------------------------------------------------------------------
// Kernel 1: stable ascending sort of each batch row (matches jnp.argsort).
// (verified in R4)
// ---------------------------------------------------------------------------
__global__ void __launch_bounds__(512) sort_kernel(const float* __restrict__ spikes)
{
    __shared__ unsigned long long keys[NPRE];
    const int b   = blockIdx.x;
    const int tid = threadIdx.x;

    for (int i = tid; i < NPRE; i += 512) {
        float v = spikes[b * NPRE + i];
        unsigned int bits = __float_as_uint(v);
        bits = (bits & 0x80000000u) ? ~bits : (bits | 0x80000000u);
        keys[i] = ((unsigned long long)bits << 32) | (unsigned int)i;
    }
    __syncthreads();

    for (int k = 2; k <= NPRE; k <<= 1) {
        for (int j = k >> 1; j >= 32; j >>= 1) {
            #pragma unroll
            for (int rep = 0; rep < NPRE / 512; ++rep) {
                int i = tid + rep * 512;
                int ixj = i ^ j;
                if (ixj > i) {
                    unsigned long long A = keys[i];
                    unsigned long long C = keys[ixj];
                    bool up = ((i & k) == 0);
                    if ((A > C) == up) { keys[i] = C; keys[ixj] = A; }
                }
            }
            __syncthreads();
        }
        unsigned long long v0 = keys[tid];
        unsigned long long v1 = keys[tid + 512];
        const bool up0 = ((tid & k) == 0);
        const bool up1 = (((tid + 512) & k) == 0);
        #pragma unroll
        for (int j = 16; j >= 1; j >>= 1) {
            if (j < k) {
                bool lower = ((tid & j) == 0);
                unsigned long long p0 = __shfl_xor_sync(0xffffffffu, v0, j);
                unsigned long long p1 = __shfl_xor_sync(0xffffffffu, v1, j);
                bool km0 = (lower == up0);
                bool km1 = (lower == up1);
                unsigned long long mn0 = (v0 < p0) ? v0 : p0;
                unsigned long long mx0 = (v0 < p0) ? p0 : v0;
                unsigned long long mn1 = (v1 < p1) ? v1 : p1;
                unsigned long long mx1 = (v1 < p1) ? p1 : v1;
                v0 = km0 ? mn0 : mx0;
                v1 = km1 ? mn1 : mx1;
            }
        }
        keys[tid]       = v0;
        keys[tid + 512] = v1;
        __syncthreads();
    }

    for (int i = tid; i < NPRE; i += 512) {
        unsigned long long kk = keys[i];
        unsigned int hi = (unsigned int)(kk >> 32);
        unsigned int bits = (hi & 0x80000000u) ? (hi ^ 0x80000000u) : ~hi;
        float s = __uint_as_float(bits);
        float e = expf(s);
        g_sorted[b * NPRE + i] = s;
        g_exp[b * NPRE + i]    = e;
        g_se[b * NPRE + i]     = s * e;
        g_idx[b * NPRE + i]    = (int)(kk & 0xFFFFFFFFu);
    }
}

// ---------------------------------------------------------------------------
// Lambert W0 on [-1/e, 0): same clip/init/Halley form as the reference.
// ---------------------------------------------------------------------------
__device__ __forceinline__ float lambertw0_dev(float z)
{
    float zc = fminf(fmaxf(z, -INV_E_F + 1e-8f), -1e-30f);
    float w;
    if (zc < -0.2f)
        w = -1.0f + sqrtf(2.0f * fmaf(E_F, zc, 1.0f));
    else
        w = zc * (1.0f - zc);
    #pragma unroll
    for (int it = 0; it < 6; ++it) {
        float ew  = __expf(w);
        float f   = fmaf(w, ew, -zc);
        float wp1 = w + 1.0f;
        float denom = fmaf(2.0f * ew * wp1, wp1, -(w + 2.0f) * f);
        w = w - __fdividef(f * 2.0f * wp1, denom);
    }
    return w;
}

// ---------------------------------------------------------------------------
// Kernel 2: fully parallel chunked causal scan, software-pipelined.
//   Block = (batch, 64-neuron group); thread (q,n) owns slice q (8 ks) of
//   neuron n each chunk, weights held in registers (prefetched 1 chunk ahead).
//   Per chunk: A) slice partial sums -> shared; prefetch next chunk;
//              B1 barrier (+ early-exit vote);
//              C) each thread: slice-start prefix from a_run + pa[q'<q],
//                 8 exact gates (a*s_next - b >= e_next, provably equivalent
//                 to z >= -1/e AND t <= s_next), Lambert on pass (rare),
//                 first-in-slice candidate -> shared; q==7 updates a_run;
//              B2 barrier;
//              D) all 8 threads of a neuron scan the 8 candidate slots,
//                 min-k wins (first valid == global min since w >= 0);
//                 q==0 writes the output once.
// ---------------------------------------------------------------------------
__global__ void __launch_bounds__(NTHR) scan_kernel(const float* __restrict__ Wmat,
                                                    float* __restrict__ out)
{
    __shared__ float sh_s[2][CH + 1];
    __shared__ float sh_e[2][CH + 1];
    __shared__ float sh_se[2][CH];
    __shared__ float sh_pa[NSUB][NT];
    __shared__ float sh_pb[NSUB][NT];
    __shared__ int   sh_ck[NSUB][NT];   // candidate local k (0..CH-1), 127 = none
    __shared__ float sh_ct[NSUB][NT];   // candidate t
    __shared__ float sh_arun[NT];
    __shared__ float sh_brun[NT];

    const int b    = blockIdx.x / NGRP;
    const int grp  = blockIdx.x % NGRP;
    const int tid  = threadIdx.x;
    const int q    = tid >> 6;          // slice 0..7 (uniform per warp-pair)
    const int n    = tid & 63;          // neuron within group
    const int ng   = grp * NT + n;      // global output neuron
    const int base = b * NPRE;

    bool done = false;

    // ---- prologue: stage chunk-0 metadata, prefetch chunk-0 weights ----
    if (tid <= CH) {
        int k = base + tid;
        sh_s[0][tid] = g_sorted[k];
        sh_e[0][tid] = g_exp[k];
        if (tid < CH) sh_se[0][tid] = g_se[k];
    }
    if (tid < NT) { sh_arun[tid] = 0.0f; sh_brun[tid] = 0.0f; }

    float wreg[KSUB];
    #pragma unroll
    for (int kk = 0; kk < KSUB; ++kk) {
        int row = __ldg(&g_idx[base + q * KSUB + kk]);
        wreg[kk] = __ldg(&Wmat[row * NPOST + ng]);
    }
    __syncthreads();

    for (int c = 0; c < NCHUNK; ++c) {
        const int buf  = c & 1;
        const int nbuf = buf ^ 1;

        // ---- phase A: slice partial sums from register weights ----
        if (!done) {
            float pa = 0.0f, pb = 0.0f;
            #pragma unroll
            for (int kk = 0; kk < KSUB; ++kk) {
                int kc = q * KSUB + kk;
                pa = fmaf(wreg[kk], sh_e[buf][kc],  pa);
                pb = fmaf(wreg[kk], sh_se[buf][kc], pb);
            }
            sh_pa[q][n] = pa;
            sh_pb[q][n] = pb;
        }
        // stage next chunk metadata
        if (tid <= CH) {
            int k = (c + 1) * CH + tid;
            if (k < NPRE) {
                sh_s[nbuf][tid] = g_sorted[base + k];
                sh_e[nbuf][tid] = g_exp[base + k];
                if (tid < CH) sh_se[nbuf][tid] = g_se[base + k];
            } else {
                sh_s[nbuf][tid] = INFINITY;
                sh_e[nbuf][tid] = INFINITY;
                if (tid < CH) sh_se[nbuf][tid] = INFINITY;
            }
        }
        // prefetch next chunk weights into registers
        float wnext[KSUB];
        if (!done && c + 1 < NCHUNK) {
            #pragma unroll
            for (int kk = 0; kk < KSUB; ++kk) {
                int row = __ldg(&g_idx[base + (c + 1) * CH + q * KSUB + kk]);
                wnext[kk] = __ldg(&Wmat[row * NPOST + ng]);
            }
        }

        if (__syncthreads_and((int)done)) break;   // B1 + early-exit vote

        // ---- phase C: exact gates from register weights ----
        if (!done) {
            float aa = sh_arun[n];
            float bb = sh_brun[n];
            for (int qq = 0; qq < q; ++qq) {       // uniform per warp
                aa += sh_pa[qq][n];
                bb += sh_pb[qq][n];
            }
            int   ck = 127;
            float ct = 0.0f;
            bool  found = false;
            #pragma unroll
            for (int kk = 0; kk < KSUB; ++kk) {
                if (!found) {
                    int kc = q * KSUB + kk;
                    aa = fmaf(wreg[kk], sh_e[buf][kc],  aa);
                    bb = fmaf(wreg[kk], sh_se[buf][kc], bb);
                    // exact gate: z >= -1/e AND t <= s_next
                    if (fmaf(aa, sh_s[buf][kc + 1], -bb) >= sh_e[buf][kc + 1]) {
                        float r = __fdividef(bb, aa);
                        float z = -__fdividef(__expf(r), aa);
                        bool valid = (aa > 0.0f) && (z >= -INV_E_F);
                        float t = r - lambertw0_dev(z);
                        if (valid && t >= sh_s[buf][kc]) {   // causal lower bound
                            ck = kc; ct = t; found = true;   // first valid in slice
                        }
                    }
                }
            }
            sh_ck[q][n] = ck;
            sh_ct[q][n] = ct;
            if (q == NSUB - 1 && !found) {          // full-chunk totals
                sh_arun[n] = aa;
                sh_brun[n] = bb;
            } else if (q == NSUB - 1) {
                // fired this chunk; a_run no longer needed but keep sane
                sh_arun[n] = aa;
                sh_brun[n] = bb;
            }
        }
        __syncthreads();                            // B2

        // ---- phase D: redundant min-k scan (all 8 threads of neuron n) ----
        if (!done) {
            int   bestk = 127, bestq = 0;
            #pragma unroll
            for (int qq = 0; qq < NSUB; ++qq) {
                int k2 = sh_ck[qq][n];
                if (k2 < bestk) { bestk = k2; bestq = qq; }
            }
            if (bestk < 127) {
                done = true;
                if (q == 0) out[b * NPOST + ng] = sh_ct[bestq][n];
            }
        }

        #pragma unroll
        for (int kk = 0; kk < KSUB; ++kk) wreg[kk] = wnext[kk];
    }

    if (!done && q == 0) out[b * NPOST + ng] = INFINITY;
}

// ---------------------------------------------------------------------------
extern "C" void kernel_launch(void* const* d_in, const int* in_sizes, int n_in,
                              void* d_out, int out_size)
{
    const float* spikes  = (const float*)d_in[0];
    const float* weights = (const float*)d_in[1];
    int sz = in_sizes[0];
    if (n_in >= 2 && in_sizes[0] > in_sizes[1]) {   // robustness to input order
        const float* t = spikes; spikes = weights; weights = t;
        sz = in_sizes[1];
    }
    int B = sz / NPRE;
    sort_kernel<<<B, 512>>>(spikes);
    scan_kernel<<<B * NGRP, NTHR>>>(weights, (float*)d_out);
}